// round 1
// baseline (speedup 1.0000x reference)
#include <cuda_runtime.h>
#include <cuda_bf16.h>
#include <math.h>

// Problem dims
#define CDIM 16
#define PDIM 256
#define DMOD 512
#define DIN  1024
#define DSTATE 16
#define DDT  32
#define NROWS (CDIM*PDIM)          // 4096

// ---------------- scratch (device globals; no allocation allowed) ----------
__device__ float g_xz[NROWS * 2 * DIN];          // in-proj output [4096,2048]
__device__ float g_im2col[(size_t)NROWS * 4 * DIN]; // [4096,4096]
__device__ float g_xiact[NROWS * DIN];           // gelu(conv)      [4096,1024]
__device__ float g_xdb[NROWS * (DDT + 2*DSTATE)];// param proj      [4096,64]
__device__ float g_dt[NROWS * DIN];              // dt pre-softplus [4096,1024]
__device__ float g_ypre[NROWS * DIN];            // scan output     [4096,1024]

typedef unsigned long long u64;

__device__ __forceinline__ u64 pack2(float x, float y) {
    u64 r;
    asm("mov.b64 %0, {%1, %2};" : "=l"(r)
        : "r"(__float_as_uint(x)), "r"(__float_as_uint(y)));
    return r;
}
__device__ __forceinline__ void unpack2(u64 v, float& x, float& y) {
    unsigned lo, hi;
    asm("mov.b64 {%0, %1}, %2;" : "=r"(lo), "=r"(hi) : "l"(v));
    x = __uint_as_float(lo);
    y = __uint_as_float(hi);
}
__device__ __forceinline__ void ffma2(u64& d, u64 a, u64 b) {
    // packed f32x2 FMA: d.lo = a.lo*b.lo + d.lo ; d.hi = a.hi*b.hi + d.hi
    asm("fma.rn.f32x2 %0, %1, %2, %0;" : "+l"(d) : "l"(a), "l"(b));
}

// jax.nn.gelu default (approximate=True, tanh form)
__device__ __forceinline__ float gelu_f(float x) {
    float inner = 0.7978845608028654f * fmaf(0.044715f * x, x * x, x);
    float t = tanhf(inner);
    return 0.5f * x * (1.0f + t);
}
// jax.nn.softplus, numerically stable
__device__ __forceinline__ float softplus_f(float x) {
    return fmaxf(x, 0.0f) + log1pf(expf(-fabsf(x)));
}

// ---------------------------------------------------------------------------
// GEMM (NT): C[M,N] = A[M,K] @ B[N,K]^T + bias[N], optional gelu epilogue.
// 128x128 block tile, K-tile 32, 256 threads, 8x8 microtile, f32x2 packed FMA.
// Requires: M % 128 == 0, K % 32 == 0, N % 8 == 0, all pointers 16B aligned,
// lda/ldb/ldc multiples of 4.
// ---------------------------------------------------------------------------
#define BM 128
#define BN 128
#define BK 32
#define SPAD 4

__global__ __launch_bounds__(256, 2) void gemm_nt(
    const float* __restrict__ A, const float* __restrict__ B,
    const float* __restrict__ bias, float* __restrict__ C,
    int M, int N, int K, int lda, int ldb, int ldc, int epi)
{
    __shared__ __align__(16) float As[BK][BM + SPAD];
    __shared__ __align__(16) float Bs[BK][BN + SPAD];

    const int tid = threadIdx.x;
    const int bm = blockIdx.y * BM;
    const int bn = blockIdx.x * BN;
    const int tx = tid & 15;   // n direction (16 x 8 = 128)
    const int ty = tid >> 4;   // m direction (16 x 8 = 128)

    u64 acc[4][8];             // acc[q][cc]: rows (ty*8+2q, ty*8+2q+1), col tx*8+cc
#pragma unroll
    for (int q = 0; q < 4; q++)
#pragma unroll
        for (int cc = 0; cc < 8; cc++) acc[q][cc] = 0ull;

    for (int k0 = 0; k0 < K; k0 += BK) {
        // Load A tile: 128 rows x 32 k = 1024 float4 / 256 threads = 4 each
#pragma unroll
        for (int j = 0; j < 4; j++) {
            int idx = tid + 256 * j;
            int row = idx >> 3;       // 0..127
            int kq  = idx & 7;        // 0..7
            float4 v = *(const float4*)(A + (size_t)(bm + row) * lda + (k0 + kq * 4));
            As[kq * 4 + 0][row] = v.x;
            As[kq * 4 + 1][row] = v.y;
            As[kq * 4 + 2][row] = v.z;
            As[kq * 4 + 3][row] = v.w;
        }
        // Load B tile (guard rows beyond N with zeros)
#pragma unroll
        for (int j = 0; j < 4; j++) {
            int idx = tid + 256 * j;
            int row = idx >> 3;
            int kq  = idx & 7;
            float4 v = make_float4(0.f, 0.f, 0.f, 0.f);
            if (bn + row < N)
                v = *(const float4*)(B + (size_t)(bn + row) * ldb + (k0 + kq * 4));
            Bs[kq * 4 + 0][row] = v.x;
            Bs[kq * 4 + 1][row] = v.y;
            Bs[kq * 4 + 2][row] = v.z;
            Bs[kq * 4 + 3][row] = v.w;
        }
        __syncthreads();

#pragma unroll
        for (int kk = 0; kk < BK; kk++) {
            const u64* ap = (const u64*)&As[kk][ty * 8];
            u64 a0 = ap[0], a1 = ap[1], a2 = ap[2], a3 = ap[3];
            const float* bp = &Bs[kk][tx * 8];
            float4 blo = *(const float4*)(bp);
            float4 bhi = *(const float4*)(bp + 4);
            float bsc[8] = {blo.x, blo.y, blo.z, blo.w, bhi.x, bhi.y, bhi.z, bhi.w};
            u64 bb[8];
#pragma unroll
            for (int cc = 0; cc < 8; cc++) bb[cc] = pack2(bsc[cc], bsc[cc]);
#pragma unroll
            for (int cc = 0; cc < 8; cc++) {
                ffma2(acc[0][cc], a0, bb[cc]);
                ffma2(acc[1][cc], a1, bb[cc]);
                ffma2(acc[2][cc], a2, bb[cc]);
                ffma2(acc[3][cc], a3, bb[cc]);
            }
        }
        __syncthreads();
    }

    // Epilogue: bias + optional gelu, vectorized float4 stores
#pragma unroll
    for (int q = 0; q < 4; q++) {
        float r0[8], r1[8];
#pragma unroll
        for (int cc = 0; cc < 8; cc++) unpack2(acc[q][cc], r0[cc], r1[cc]);
        int m0 = bm + ty * 8 + q * 2;
#pragma unroll
        for (int half = 0; half < 2; half++) {
            int col = bn + tx * 8 + half * 4;
            if (col < N) {
                float4 bv = *(const float4*)(bias + col);
                float4 v0, v1;
                v0.x = r0[half * 4 + 0] + bv.x;
                v0.y = r0[half * 4 + 1] + bv.y;
                v0.z = r0[half * 4 + 2] + bv.z;
                v0.w = r0[half * 4 + 3] + bv.w;
                v1.x = r1[half * 4 + 0] + bv.x;
                v1.y = r1[half * 4 + 1] + bv.y;
                v1.z = r1[half * 4 + 2] + bv.z;
                v1.w = r1[half * 4 + 3] + bv.w;
                if (epi == 1) {
                    v0.x = gelu_f(v0.x); v0.y = gelu_f(v0.y);
                    v0.z = gelu_f(v0.z); v0.w = gelu_f(v0.w);
                    v1.x = gelu_f(v1.x); v1.y = gelu_f(v1.y);
                    v1.z = gelu_f(v1.z); v1.w = gelu_f(v1.w);
                }
                *(float4*)(C + (size_t)m0 * ldc + col) = v0;
                *(float4*)(C + (size_t)(m0 + 1) * ldc + col) = v1;
            }
        }
    }
}

// ---------------------------------------------------------------------------
// im2col for the conv: out[row, i*4+h] = xz[c, clamp(p+h-2,0,P-1), i]
// (edge padding: left 2, right 1; conv is cross-correlation, no flip)
// Matches conv_w[o,i,h] flattened as B[o, i*4+h] => no weight transpose.
// ---------------------------------------------------------------------------
__global__ void im2col_kernel(const float* __restrict__ xz, float* __restrict__ out)
{
    int gid = blockIdx.x * blockDim.x + threadIdx.x;
    if (gid >= NROWS * DIN) return;
    int i   = gid & (DIN - 1);
    int row = gid >> 10;
    int c = row >> 8;
    int p = row & 255;
    const float* base = xz + (size_t)c * PDIM * (2 * DIN) + i;
    int pm2 = max(p - 2, 0);
    int pm1 = max(p - 1, 0);
    int pp1 = min(p + 1, PDIM - 1);
    float4 v;
    v.x = base[(size_t)pm2 * (2 * DIN)];
    v.y = base[(size_t)pm1 * (2 * DIN)];
    v.z = base[(size_t)p   * (2 * DIN)];
    v.w = base[(size_t)pp1 * (2 * DIN)];
    *(float4*)(out + (size_t)row * (4 * DIN) + i * 4) = v;
}

// ---------------------------------------------------------------------------
// Selective scan. Grid = C * (DI/64) = 256 blocks, 256 threads.
// Each thread owns (d, quarter of the 16 states): 4 exps/step, shfl reduce.
// ---------------------------------------------------------------------------
__global__ __launch_bounds__(256) void scan_kernel(
    const float* __restrict__ xiact, const float* __restrict__ xz,
    const float* __restrict__ dtlin, const float* __restrict__ xdb,
    const float* __restrict__ A_log, const float* __restrict__ Dp,
    const float* __restrict__ ssm0, float* __restrict__ ypre,
    float* __restrict__ state_out)
{
    const int tid = threadIdx.x;
    const int q  = tid & 3;          // state quarter
    const int dl = tid >> 2;         // 0..63
    const int c = blockIdx.x >> 4;
    const int d = ((blockIdx.x & 15) << 6) + dl;

    float An[4], s[4];
#pragma unroll
    for (int j = 0; j < 4; j++) {
        int n = q * 4 + j;
        An[j] = -expf(A_log[d * DSTATE + n]);
        s[j]  = ssm0[((size_t)c * DIN + d) * DSTATE + n];
    }
    const float Dd = Dp[d];

    __shared__ float bc[32];         // bc[0..15]=B, bc[16..31]=Cm (param_b already folded in)

    for (int p = 0; p < PDIM; p++) {
        int row = (c << 8) + p;
        if (tid < 32) bc[tid] = xdb[row * 64 + 32 + tid];
        __syncthreads();

        float dtv = softplus_f(dtlin[(size_t)row * DIN + d]);
        float xv  = xiact[(size_t)row * DIN + d];
        float xdt = xv * dtv;
        float y = 0.0f;
#pragma unroll
        for (int j = 0; j < 4; j++) {
            int n = q * 4 + j;
            float dA = expf(dtv * An[j]);
            s[j] = fmaf(s[j], dA, xdt * bc[n]);
            y = fmaf(s[j], bc[16 + n], y);
        }
        y += __shfl_xor_sync(0xffffffffu, y, 1);
        y += __shfl_xor_sync(0xffffffffu, y, 2);
        if (q == 0) {
            float zv = xz[(size_t)row * (2 * DIN) + DIN + d];
            // double gelu on z (faithful to the source)
            ypre[(size_t)row * DIN + d] = (y + Dd * xv) * gelu_f(gelu_f(zv));
        }
        __syncthreads();
    }

    if (state_out) {
#pragma unroll
        for (int j = 0; j < 4; j++)
            state_out[((size_t)c * DIN + d) * DSTATE + q * 4 + j] = s[j];
    }
}

// ---------------------------------------------------------------------------
extern "C" void kernel_launch(void* const* d_in, const int* in_sizes, int n_in,
                              void* d_out, int out_size)
{
    const float* x       = (const float*)d_in[0];
    const float* ssm0    = (const float*)d_in[1];
    const float* in_w    = (const float*)d_in[2];
    const float* in_b    = (const float*)d_in[3];
    const float* conv_w  = (const float*)d_in[4];
    const float* conv_b  = (const float*)d_in[5];
    const float* param_w = (const float*)d_in[6];
    const float* param_b = (const float*)d_in[7];
    const float* dt_w    = (const float*)d_in[8];
    const float* dt_b    = (const float*)d_in[9];
    const float* out_w   = (const float*)d_in[10];
    const float* out_b   = (const float*)d_in[11];
    const float* A_log   = (const float*)d_in[12];
    const float* Dp      = (const float*)d_in[13];
    float* out = (float*)d_out;

    float *p_xz, *p_i2c, *p_xiact, *p_xdb, *p_dt, *p_ypre;
    cudaGetSymbolAddress((void**)&p_xz,    g_xz);
    cudaGetSymbolAddress((void**)&p_i2c,   g_im2col);
    cudaGetSymbolAddress((void**)&p_xiact, g_xiact);
    cudaGetSymbolAddress((void**)&p_xdb,   g_xdb);
    cudaGetSymbolAddress((void**)&p_dt,    g_dt);
    cudaGetSymbolAddress((void**)&p_ypre,  g_ypre);

    const int y_elems = NROWS * DMOD;                 // 2097152
    const int s_elems = CDIM * DIN * DSTATE;          // 262144
    float* state_out = (out_size >= y_elems + s_elems) ? (out + y_elems) : nullptr;

    // 1) in-proj: xz = x @ in_w^T + in_b        [4096,2048]
    gemm_nt<<<dim3(2048 / BN, NROWS / BM), 256>>>(
        x, in_w, in_b, p_xz, NROWS, 2048, DMOD, DMOD, DMOD, 2048, 0);

    // 2) im2col of the x-branch (edge-padded taps)
    im2col_kernel<<<(NROWS * DIN) / 256, 256>>>(p_xz, p_i2c);

    // 3) conv as GEMM + conv_b + gelu fused:    [4096,1024], K=4096
    gemm_nt<<<dim3(DIN / BN, NROWS / BM), 256>>>(
        p_i2c, conv_w, conv_b, p_xiact, NROWS, DIN, 4 * DIN, 4 * DIN, 4 * DIN, DIN, 1);

    // 4) param proj: xdb = xi @ param_w^T + param_b   [4096,64]
    gemm_nt<<<dim3(1, NROWS / BM), 256>>>(
        p_xiact, param_w, param_b, p_xdb, NROWS, DDT + 2 * DSTATE, DIN, DIN, DIN, 64, 0);

    // 5) dt proj: dt_lin = xdb[:, :32] @ dt_w^T + dt_b   [4096,1024], K=32
    gemm_nt<<<dim3(DIN / BN, NROWS / BM), 256>>>(
        p_xdb, dt_w, dt_b, p_dt, NROWS, DIN, DDT, 64, DDT, DIN, 0);

    // 6) selective scan (softplus, dA=exp(dt*A), recurrence, y, double-gelu z)
    scan_kernel<<<256, 256>>>(p_xiact, p_xz, p_dt, p_xdb, A_log, Dp, ssm0,
                              p_ypre, state_out);

    // 7) out proj: y @ out_w^T + out_b  ->  d_out  [4096,512]
    gemm_nt<<<dim3(DMOD / BN, NROWS / BM), 256>>>(
        p_ypre, out_w, out_b, out, NROWS, DMOD, DIN, DIN, DIN, DMOD, 0);
}

// round 4
// speedup vs baseline: 2.1400x; 2.1400x over previous
#include <cuda_runtime.h>
#include <cuda_bf16.h>
#include <math.h>
#include <stdint.h>

// Problem dims
#define CDIM 16
#define PDIM 256
#define DMOD 512
#define DIN  1024
#define DSTATE 16
#define DDT  32
#define NROWS (CDIM*PDIM)          // 4096

typedef unsigned int u32;
typedef __nv_bfloat16 bf16;

// ---------------- scratch (device globals; no allocation allowed) ----------
__device__ float g_xz[NROWS * 2 * DIN];            // in-proj out fp32 [4096,2048]
__device__ float g_xiact[NROWS * DIN];             // gelu(conv) fp32  [4096,1024]
__device__ float g_xdb[NROWS * 64];                // param proj fp32  [4096,64]
__device__ float g_dtlin[NROWS * DIN];             // dt pre-softplus  [4096,1024]

__device__ bf16 g_xh[NROWS * DMOD],        g_xl[NROWS * DMOD];          // x hi/lo
__device__ bf16 g_inwh[2*DIN * DMOD],      g_inwl[2*DIN * DMOD];        // in_w
__device__ bf16 g_i2ch[(size_t)NROWS*4*DIN], g_i2cl[(size_t)NROWS*4*DIN]; // im2col
__device__ bf16 g_cwh[DIN * 4*DIN],        g_cwl[DIN * 4*DIN];          // conv_w
__device__ bf16 g_xiah[NROWS * DIN],       g_xial[NROWS * DIN];         // gelu(conv)
__device__ bf16 g_pwh[64 * DIN],           g_pwl[64 * DIN];             // param_w
__device__ bf16 g_dtah[NROWS * 64],        g_dtal[NROWS * 64];          // dt A (pad 64)
__device__ bf16 g_dtwh[DIN * 64],          g_dtwl[DIN * 64];            // dt_w (pad 64)
__device__ bf16 g_yh[NROWS * DIN],         g_yl[NROWS * DIN];           // scan out
__device__ bf16 g_owh[DMOD * DIN],         g_owl[DMOD * DIN];           // out_w

// ------------------------- PTX helpers (arch-generic only) -----------------
__device__ __forceinline__ void ldsm4(u32& r0, u32& r1, u32& r2, u32& r3, u32 addr) {
    asm volatile("ldmatrix.sync.aligned.m8n8.x4.shared.b16 {%0,%1,%2,%3}, [%4];"
                 : "=r"(r0), "=r"(r1), "=r"(r2), "=r"(r3) : "r"(addr));
}
__device__ __forceinline__ void mma16816(float* d, const u32* a, const u32* b) {
    asm volatile(
        "mma.sync.aligned.m16n8k16.row.col.f32.bf16.bf16.f32 "
        "{%0,%1,%2,%3},{%4,%5,%6,%7},{%8,%9},{%0,%1,%2,%3};"
        : "+f"(d[0]), "+f"(d[1]), "+f"(d[2]), "+f"(d[3])
        : "r"(a[0]), "r"(a[1]), "r"(a[2]), "r"(a[3]), "r"(b[0]), "r"(b[1]));
}
__device__ __forceinline__ void cp16(u32 dst, const void* src, int srcsize) {
    asm volatile("cp.async.cg.shared.global [%0], [%1], 16, %2;"
                 :: "r"(dst), "l"(src), "r"(srcsize) : "memory");
}
#define CP_COMMIT() asm volatile("cp.async.commit_group;" ::: "memory")
#define CP_WAIT1()  asm volatile("cp.async.wait_group 1;" ::: "memory")

// 64B-row swizzle: XOR 16B-chunk index (bits 4-5) with row bits (bits 7-8).
// Conflict-free for both the cp.async stores and ldmatrix loads.
#define SW64(o) ((u32)(o) ^ ((((u32)(o)) >> 3) & 0x30))

// --------------------------- math helpers ----------------------------------
__device__ __forceinline__ float gelu_f(float x) {
    float inner = 0.7978845608028654f * fmaf(0.044715f * x, x * x, x);
    return 0.5f * x * (1.0f + tanhf(inner));
}
__device__ __forceinline__ float softplus_f(float x) {
    return fmaxf(x, 0.0f) + log1pf(expf(-fabsf(x)));
}

// ---------------------------------------------------------------------------
// HMMA GEMM (NT): C[M,N] = (Ah+Al)[M,K] @ (Bh+Bl)[N,K]^T + bias[N]
// bf16x3 split: Ah*Bh + Ah*Bl + Al*Bh into fp32 accum (mma.sync m16n8k16).
// BM=BN=128, BK=32, 256 threads (8 warps, 4m x 2n, 32x64 warp tile),
// cp.async 2-stage pipeline. flags: 1=gelu, 2=write fp32 C, 4=write bf16 Oh/Ol
// ---------------------------------------------------------------------------
#define TILE_BYTES 8192                 // 128 rows x 64 B
#define STAGE_BYTES (4 * TILE_BYTES)    // Ah, Al, Bh, Bl
#define GEMM_SMEM (2 * STAGE_BYTES)     // 65536

__device__ __forceinline__ void load_stage(
    u32 sbase, const bf16* __restrict__ Ah, const bf16* __restrict__ Al,
    const bf16* __restrict__ Bh, const bf16* __restrict__ Bl,
    int bm, int bn, int N, int K, int k0, int tid)
{
#pragma unroll
    for (int j = 0; j < 2; j++) {
        int linear = tid + j * 256;
        int row = linear >> 2;
        int c = linear & 3;
        u32 sw = SW64(row * 64 + c * 16);
        size_t goff = (size_t)(bm + row) * K + k0 + c * 8;
        cp16(sbase + sw, Ah + goff, 16);
        cp16(sbase + TILE_BYTES + sw, Al + goff, 16);
        int bvalid = (bn + row < N) ? 16 : 0;
        size_t gob = (size_t)(bn + (bvalid ? row : 0)) * K + k0 + c * 8;
        cp16(sbase + 2 * TILE_BYTES + sw, Bh + gob, bvalid);
        cp16(sbase + 3 * TILE_BYTES + sw, Bl + gob, bvalid);
    }
}

__global__ __launch_bounds__(256) void gemm_hmma(
    const bf16* __restrict__ Ah, const bf16* __restrict__ Al,
    const bf16* __restrict__ Bh, const bf16* __restrict__ Bl,
    const float* __restrict__ bias, float* __restrict__ C,
    bf16* __restrict__ Oh, bf16* __restrict__ Ol,
    int M, int N, int K, int flags)
{
    extern __shared__ __align__(128) char smem[];
    const u32 sb = (u32)__cvta_generic_to_shared(smem);
    const int tid = threadIdx.x;
    const int lane = tid & 31;
    const int wid = tid >> 5;
    const int warp_m = wid & 3;     // * 32
    const int warp_n = wid >> 2;    // * 64

    const int bm = blockIdx.y * 128;
    const int bn = blockIdx.x * 128;
    const int nch = K >> 5;

    float acc[2][8][4];
#pragma unroll
    for (int mt = 0; mt < 2; mt++)
#pragma unroll
        for (int nt = 0; nt < 8; nt++)
#pragma unroll
            for (int i = 0; i < 4; i++) acc[mt][nt][i] = 0.0f;

    load_stage(sb, Ah, Al, Bh, Bl, bm, bn, N, K, 0, tid);
    CP_COMMIT();
    if (nch > 1) load_stage(sb + STAGE_BYTES, Ah, Al, Bh, Bl, bm, bn, N, K, 32, tid);
    CP_COMMIT();

    // lane-pattern pieces for ldmatrix source addressing
    const int a_row_l = lane & 15;              // row within m16 tile
    const int a_kb    = (lane >> 4) << 4;       // +16B for k8 half
    const int b_row_l = (lane & 7) + ((lane >> 4) << 3);
    const int b_kb    = ((lane >> 3) & 1) << 4;

    for (int ck = 0; ck < nch; ck++) {
        CP_WAIT1();
        __syncthreads();
        const u32 st = sb + (ck & 1) * STAGE_BYTES;

#pragma unroll
        for (int ks = 0; ks < 2; ks++) {
            u32 ah[2][4], al[2][4];
#pragma unroll
            for (int mt = 0; mt < 2; mt++) {
                u32 o = (u32)((warp_m * 32 + mt * 16 + a_row_l) * 64 + ks * 32 + a_kb);
                u32 so = SW64(o);
                ldsm4(ah[mt][0], ah[mt][1], ah[mt][2], ah[mt][3], st + so);
                ldsm4(al[mt][0], al[mt][1], al[mt][2], al[mt][3], st + TILE_BYTES + so);
            }
#pragma unroll
            for (int nt16 = 0; nt16 < 4; nt16++) {
                u32 o = (u32)((warp_n * 64 + nt16 * 16 + b_row_l) * 64 + ks * 32 + b_kb);
                u32 so = SW64(o);
                u32 bh[4], bl[4];
                ldsm4(bh[0], bh[1], bh[2], bh[3], st + 2 * TILE_BYTES + so);
                ldsm4(bl[0], bl[1], bl[2], bl[3], st + 3 * TILE_BYTES + so);
#pragma unroll
                for (int mt = 0; mt < 2; mt++) {
                    mma16816(acc[mt][nt16 * 2], ah[mt], bh);
                    mma16816(acc[mt][nt16 * 2], ah[mt], bl);
                    mma16816(acc[mt][nt16 * 2], al[mt], bh);
                    mma16816(acc[mt][nt16 * 2 + 1], ah[mt], bh + 2);
                    mma16816(acc[mt][nt16 * 2 + 1], ah[mt], bl + 2);
                    mma16816(acc[mt][nt16 * 2 + 1], al[mt], bh + 2);
                }
            }
        }
        __syncthreads();
        if (ck + 2 < nch)
            load_stage(sb + (ck & 1) * STAGE_BYTES, Ah, Al, Bh, Bl, bm, bn, N, K,
                       (ck + 2) * 32, tid);
        CP_COMMIT();
    }

    // epilogue
#pragma unroll
    for (int mt = 0; mt < 2; mt++) {
#pragma unroll
        for (int nt = 0; nt < 8; nt++) {
            int row0 = bm + warp_m * 32 + mt * 16 + (lane >> 2);
            int col = bn + warp_n * 64 + nt * 8 + (lane & 3) * 2;
            if (col < N) {
                float b0 = __ldg(bias + col), b1 = __ldg(bias + col + 1);
                float v00 = acc[mt][nt][0] + b0, v01 = acc[mt][nt][1] + b1;
                float v10 = acc[mt][nt][2] + b0, v11 = acc[mt][nt][3] + b1;
                if (flags & 1) {
                    v00 = gelu_f(v00); v01 = gelu_f(v01);
                    v10 = gelu_f(v10); v11 = gelu_f(v11);
                }
                if (flags & 2) {
                    *(float2*)(C + (size_t)row0 * N + col) = make_float2(v00, v01);
                    *(float2*)(C + (size_t)(row0 + 8) * N + col) = make_float2(v10, v11);
                }
                if (flags & 4) {
                    bf16 h00 = __float2bfloat16(v00), h01 = __float2bfloat16(v01);
                    bf16 h10 = __float2bfloat16(v10), h11 = __float2bfloat16(v11);
                    *(__nv_bfloat162*)(Oh + (size_t)row0 * N + col) = __nv_bfloat162(h00, h01);
                    *(__nv_bfloat162*)(Oh + (size_t)(row0 + 8) * N + col) = __nv_bfloat162(h10, h11);
                    bf16 l00 = __float2bfloat16(v00 - __bfloat162float(h00));
                    bf16 l01 = __float2bfloat16(v01 - __bfloat162float(h01));
                    bf16 l10 = __float2bfloat16(v10 - __bfloat162float(h10));
                    bf16 l11 = __float2bfloat16(v11 - __bfloat162float(h11));
                    *(__nv_bfloat162*)(Ol + (size_t)row0 * N + col) = __nv_bfloat162(l00, l01);
                    *(__nv_bfloat162*)(Ol + (size_t)(row0 + 8) * N + col) = __nv_bfloat162(l10, l11);
                }
            }
        }
    }
}

// ---------------------------------------------------------------------------
// fp32 -> bf16 hi/lo split (elementwise, float4 vectorized)
// ---------------------------------------------------------------------------
__global__ void cvt_hilo(const float* __restrict__ src, bf16* __restrict__ hi,
                         bf16* __restrict__ lo, int n4)
{
    int gid = blockIdx.x * blockDim.x + threadIdx.x;
    if (gid >= n4) return;
    float4 v = *(const float4*)(src + gid * 4);
    float a[4] = {v.x, v.y, v.z, v.w};
    bf16 h[4], l[4];
#pragma unroll
    for (int i = 0; i < 4; i++) {
        h[i] = __float2bfloat16(a[i]);
        l[i] = __float2bfloat16(a[i] - __bfloat162float(h[i]));
    }
    *(__nv_bfloat162*)(hi + gid * 4)     = __nv_bfloat162(h[0], h[1]);
    *(__nv_bfloat162*)(hi + gid * 4 + 2) = __nv_bfloat162(h[2], h[3]);
    *(__nv_bfloat162*)(lo + gid * 4)     = __nv_bfloat162(l[0], l[1]);
    *(__nv_bfloat162*)(lo + gid * 4 + 2) = __nv_bfloat162(l[2], l[3]);
}

// padded variant: out[row,k] = (k < cols ? src[row*src_ld+k] : 0), outK wide
__global__ void cvt_pad(const float* __restrict__ src, bf16* __restrict__ hi,
                        bf16* __restrict__ lo, int rows, int src_ld, int cols, int outK)
{
    int gid = blockIdx.x * blockDim.x + threadIdx.x;
    if (gid >= rows * outK) return;
    int k = gid % outK, r = gid / outK;
    float v = (k < cols) ? src[(size_t)r * src_ld + k] : 0.0f;
    bf16 h = __float2bfloat16(v);
    hi[gid] = h;
    lo[gid] = __float2bfloat16(v - __bfloat162float(h));
}

// ---------------------------------------------------------------------------
// im2col producing bf16 hi/lo: out[row, i*4+h] = xz[c, clamp(p+h-2,0,P-1), i]
// ---------------------------------------------------------------------------
__global__ void im2col_hilo(const float* __restrict__ xz, bf16* __restrict__ hi,
                            bf16* __restrict__ lo)
{
    int gid = blockIdx.x * blockDim.x + threadIdx.x;
    if (gid >= NROWS * DIN) return;
    int i = gid & (DIN - 1);
    int row = gid >> 10;
    int c = row >> 8, p = row & 255;
    const float* base = xz + (size_t)c * PDIM * (2 * DIN) + i;
    float t[4];
    t[0] = base[(size_t)max(p - 2, 0) * (2 * DIN)];
    t[1] = base[(size_t)max(p - 1, 0) * (2 * DIN)];
    t[2] = base[(size_t)p * (2 * DIN)];
    t[3] = base[(size_t)min(p + 1, PDIM - 1) * (2 * DIN)];
    bf16 h[4], l[4];
#pragma unroll
    for (int j = 0; j < 4; j++) {
        h[j] = __float2bfloat16(t[j]);
        l[j] = __float2bfloat16(t[j] - __bfloat162float(h[j]));
    }
    size_t o = (size_t)row * (4 * DIN) + i * 4;
    *(__nv_bfloat162*)(hi + o)     = __nv_bfloat162(h[0], h[1]);
    *(__nv_bfloat162*)(hi + o + 2) = __nv_bfloat162(h[2], h[3]);
    *(__nv_bfloat162*)(lo + o)     = __nv_bfloat162(l[0], l[1]);
    *(__nv_bfloat162*)(lo + o + 2) = __nv_bfloat162(l[2], l[3]);
}

// ---------------------------------------------------------------------------
// Selective scan. Grid = C*(DI/64) = 256 blocks x 256 threads.
// ---------------------------------------------------------------------------
__global__ __launch_bounds__(256) void scan_kernel(
    const float* __restrict__ xiact, const float* __restrict__ xz,
    const float* __restrict__ dtlin, const float* __restrict__ xdb,
    const float* __restrict__ A_log, const float* __restrict__ Dp,
    const float* __restrict__ ssm0, bf16* __restrict__ yh, bf16* __restrict__ yl,
    float* __restrict__ state_out)
{
    __shared__ float bcs[PDIM][32];
    const int tid = threadIdx.x;
    const int q = tid & 3;
    const int dl = tid >> 2;
    const int c = blockIdx.x >> 4;
    const int d = ((blockIdx.x & 15) << 6) + dl;

    for (int i = tid; i < PDIM * 32; i += 256) {
        int p = i >> 5, n = i & 31;
        bcs[p][n] = xdb[(size_t)((c << 8) + p) * 64 + 32 + n];
    }

    float An[4], s[4];
#pragma unroll
    for (int j = 0; j < 4; j++) {
        int n = q * 4 + j;
        An[j] = -expf(A_log[d * DSTATE + n]);
        s[j] = ssm0[((size_t)c * DIN + d) * DSTATE + n];
    }
    const float Dd = Dp[d];
    __syncthreads();

    for (int p = 0; p < PDIM; p++) {
        int row = (c << 8) + p;
        float dtv = softplus_f(dtlin[(size_t)row * DIN + d]);
        float xv = xiact[(size_t)row * DIN + d];
        float xdt = xv * dtv;
        float y = 0.0f;
#pragma unroll
        for (int j = 0; j < 4; j++) {
            int n = q * 4 + j;
            float dA = expf(dtv * An[j]);
            s[j] = fmaf(s[j], dA, xdt * bcs[p][n]);
            y = fmaf(s[j], bcs[p][16 + n], y);
        }
        y += __shfl_xor_sync(0xffffffffu, y, 1);
        y += __shfl_xor_sync(0xffffffffu, y, 2);
        if (q == 0) {
            float zv = xz[(size_t)row * (2 * DIN) + DIN + d];
            float r = (y + Dd * xv) * gelu_f(gelu_f(zv));  // double gelu (faithful)
            bf16 h = __float2bfloat16(r);
            yh[(size_t)row * DIN + d] = h;
            yl[(size_t)row * DIN + d] = __float2bfloat16(r - __bfloat162float(h));
        }
    }

    if (state_out) {
#pragma unroll
        for (int j = 0; j < 4; j++)
            state_out[((size_t)c * DIN + d) * DSTATE + q * 4 + j] = s[j];
    }
}

// ---------------------------------------------------------------------------
extern "C" void kernel_launch(void* const* d_in, const int* in_sizes, int n_in,
                              void* d_out, int out_size)
{
    const float* x       = (const float*)d_in[0];
    const float* ssm0    = (const float*)d_in[1];
    const float* in_w    = (const float*)d_in[2];
    const float* in_b    = (const float*)d_in[3];
    const float* conv_w  = (const float*)d_in[4];
    const float* conv_b  = (const float*)d_in[5];
    const float* param_w = (const float*)d_in[6];
    const float* param_b = (const float*)d_in[7];
    const float* dt_w    = (const float*)d_in[8];
    const float* dt_b    = (const float*)d_in[9];
    const float* out_w   = (const float*)d_in[10];
    const float* out_b   = (const float*)d_in[11];
    const float* A_log   = (const float*)d_in[12];
    const float* Dp      = (const float*)d_in[13];
    float* out = (float*)d_out;

    static int smem_set = 0;
    if (!smem_set) {
        cudaFuncSetAttribute(gemm_hmma, cudaFuncAttributeMaxDynamicSharedMemorySize,
                             GEMM_SMEM);
        smem_set = 1;
    }

    float *p_xz, *p_xiact, *p_xdb, *p_dtlin;
    cudaGetSymbolAddress((void**)&p_xz, g_xz);
    cudaGetSymbolAddress((void**)&p_xiact, g_xiact);
    cudaGetSymbolAddress((void**)&p_xdb, g_xdb);
    cudaGetSymbolAddress((void**)&p_dtlin, g_dtlin);
    bf16 *xh, *xl, *inwh, *inwl, *i2ch, *i2cl, *cwh, *cwl, *xiah, *xial;
    bf16 *pwh, *pwl, *dtah, *dtal, *dtwh, *dtwl, *yh, *yl, *owh, *owl;
    cudaGetSymbolAddress((void**)&xh, g_xh);     cudaGetSymbolAddress((void**)&xl, g_xl);
    cudaGetSymbolAddress((void**)&inwh, g_inwh); cudaGetSymbolAddress((void**)&inwl, g_inwl);
    cudaGetSymbolAddress((void**)&i2ch, g_i2ch); cudaGetSymbolAddress((void**)&i2cl, g_i2cl);
    cudaGetSymbolAddress((void**)&cwh, g_cwh);   cudaGetSymbolAddress((void**)&cwl, g_cwl);
    cudaGetSymbolAddress((void**)&xiah, g_xiah); cudaGetSymbolAddress((void**)&xial, g_xial);
    cudaGetSymbolAddress((void**)&pwh, g_pwh);   cudaGetSymbolAddress((void**)&pwl, g_pwl);
    cudaGetSymbolAddress((void**)&dtah, g_dtah); cudaGetSymbolAddress((void**)&dtal, g_dtal);
    cudaGetSymbolAddress((void**)&dtwh, g_dtwh); cudaGetSymbolAddress((void**)&dtwl, g_dtwl);
    cudaGetSymbolAddress((void**)&yh, g_yh);     cudaGetSymbolAddress((void**)&yl, g_yl);
    cudaGetSymbolAddress((void**)&owh, g_owh);   cudaGetSymbolAddress((void**)&owl, g_owl);

    const int y_elems = NROWS * DMOD;
    const int s_elems = CDIM * DIN * DSTATE;
    float* state_out = (out_size >= y_elems + s_elems) ? (out + y_elems) : nullptr;

    // weight + input conversions to bf16 hi/lo
    cvt_hilo<<<(NROWS * DMOD / 4 + 255) / 256, 256>>>(x, xh, xl, NROWS * DMOD / 4);
    cvt_hilo<<<(2 * DIN * DMOD / 4 + 255) / 256, 256>>>(in_w, inwh, inwl, 2 * DIN * DMOD / 4);
    cvt_hilo<<<(DIN * 4 * DIN / 4 + 255) / 256, 256>>>(conv_w, cwh, cwl, DIN * 4 * DIN / 4);
    cvt_hilo<<<(64 * DIN / 4 + 255) / 256, 256>>>(param_w, pwh, pwl, 64 * DIN / 4);
    cvt_pad<<<(DIN * 64 + 255) / 256, 256>>>(dt_w, dtwh, dtwl, DIN, DDT, DDT, 64);
    cvt_hilo<<<(DMOD * DIN / 4 + 255) / 256, 256>>>(out_w, owh, owl, DMOD * DIN / 4);

    // 1) in-proj: xz = x @ in_w^T + in_b   [4096,2048] fp32
    gemm_hmma<<<dim3(2048 / 128, NROWS / 128), 256, GEMM_SMEM>>>(
        xh, xl, inwh, inwl, in_b, p_xz, nullptr, nullptr, NROWS, 2048, DMOD, 2);

    // 2) im2col (edge-padded taps) -> bf16 hi/lo
    im2col_hilo<<<(NROWS * DIN) / 256, 256>>>(p_xz, i2ch, i2cl);

    // 3) conv GEMM + bias + gelu -> xiact fp32 AND hi/lo   [4096,1024], K=4096
    gemm_hmma<<<dim3(DIN / 128, NROWS / 128), 256, GEMM_SMEM>>>(
        i2ch, i2cl, cwh, cwl, conv_b, p_xiact, xiah, xial, NROWS, DIN, 4 * DIN, 1 | 2 | 4);

    // 4) param proj: xdb = xi @ param_w^T + param_b   [4096,64], K=1024
    gemm_hmma<<<dim3(1, NROWS / 128), 256, GEMM_SMEM>>>(
        xiah, xial, pwh, pwl, param_b, p_xdb, nullptr, nullptr, NROWS, 64, DIN, 2);

    // 5) dt-proj A operand (first 32 cols of xdb, zero-padded to K=64)
    cvt_pad<<<(NROWS * 64 + 255) / 256, 256>>>(p_xdb, dtah, dtal, NROWS, 64, DDT, 64);

    // 6) dt proj: dtlin = dt @ dt_w^T + dt_b   [4096,1024], K=64(padded)
    gemm_hmma<<<dim3(DIN / 128, NROWS / 128), 256, GEMM_SMEM>>>(
        dtah, dtal, dtwh, dtwl, dt_b, p_dtlin, nullptr, nullptr, NROWS, DIN, 64, 2);

    // 7) selective scan -> ypre hi/lo + final state
    scan_kernel<<<256, 256>>>(p_xiact, p_xz, p_dtlin, p_xdb, A_log, Dp, ssm0,
                              yh, yl, state_out);

    // 8) out proj: y @ out_w^T + out_b -> d_out   [4096,512], K=1024
    gemm_hmma<<<dim3(DMOD / 128, NROWS / 128), 256, GEMM_SMEM>>>(
        yh, yl, owh, owl, out_b, out, nullptr, nullptr, NROWS, DMOD, DIN, 2);
}